// round 17
// baseline (speedup 1.0000x reference)
#include <cuda_runtime.h>
#include <cstdint>

// Problem constants
#define BATCH 32
#define CIN   128
#define COUT  256
#define HH    56
#define WW    56
#define HWPix (HH*WW)          // 3136
#define KTAPS 9
#define KTOT  (CIN*KTAPS)      // 1152

#define PA 144                 // A smem pitch (bytes), LDSM conflict-free
#define ABUF (64*PA)           // 9216 per tap slab (M=64 tile)
#define SMEMSZ (KTAPS*ABUF)    // 82944 : all 9 tap slabs resident, 2 CTAs/SM
#define OPITCH 68              // epilogue staging pitch in floats (272B)

// Scratch (allocation-free rule: __device__ globals)
__device__ __align__(128) int8_t g_x8[(size_t)BATCH * HWPix * CIN];     // NHWC int8
// Weights v3 fragment order: [ntile 32][tap 9][half 2][lane 32] x 16B
__device__ __align__(128) int8_t g_wfrag[32 * KTAPS * 2 * 32 * 16];     // 294912 B

// ---------------------------------------------------------------------------
// Kernel 1: merged converts.
//   blocks [0,392): x fp32 NCHW -> int8 NHWC. Thread = 4 consecutive pixels x
//                   32 channels; reads are LDG.128 (warp = 512B contiguous).
//   blocks [392,464): w fp32 OIHW -> fragment-ordered int8 (layout v3).
// ---------------------------------------------------------------------------
__global__ void convert_kernel(const float* __restrict__ x,
                               const float* __restrict__ w) {
    if (blockIdx.x < 392) {
        int tid = threadIdx.x;
        int pg  = blockIdx.x * 64 + (tid & 63);   // pixel group (4 px), 0..25087
        int cg  = tid >> 6;                       // channel group, 0..3
        int b   = pg / (HWPix / 4);
        int hwg = pg - b * (HWPix / 4);
        int hw0 = hwg * 4;
        const float* xb = x + ((size_t)b * CIN + cg * 32) * HWPix + hw0;
        uint32_t outw[32];                        // [j 4][word 8]
#pragma unroll
        for (int i = 0; i < 32; i++) outw[i] = 0;
#pragma unroll
        for (int i = 0; i < 32; i++) {            // channel cg*32 + i
            float4 f = *(const float4*)(xb + (size_t)i * HWPix);
            int wi = i >> 2, sh = (i & 3) * 8;
            outw[0 * 8 + wi] |= (uint32_t)(__float2int_rn(f.x) & 0xFF) << sh;
            outw[1 * 8 + wi] |= (uint32_t)(__float2int_rn(f.y) & 0xFF) << sh;
            outw[2 * 8 + wi] |= (uint32_t)(__float2int_rn(f.z) & 0xFF) << sh;
            outw[3 * 8 + wi] |= (uint32_t)(__float2int_rn(f.w) & 0xFF) << sh;
        }
#pragma unroll
        for (int j = 0; j < 4; j++) {
            int4* dst = (int4*)(g_x8 + (size_t)(pg * 4 + j) * CIN + cg * 32);
            dst[0] = make_int4((int)outw[j*8+0], (int)outw[j*8+1],
                               (int)outw[j*8+2], (int)outw[j*8+3]);
            dst[1] = make_int4((int)outw[j*8+4], (int)outw[j*8+5],
                               (int)outw[j*8+6], (int)outw[j*8+7]);
        }
    } else {
        // v3 entry t = (((nt*9 + tap)*2 + h)*32 + lane); 16B per entry.
        // entry holds frag(kc=2h) in bytes[0:8) and frag(kc=2h+1) in [8:16).
        // frag(kc): v0 byte j = W[n][c=kc*32+4*tig+j], v1 = same with c+16,
        // n = nt*8 + g, g=lane>>2, tig=lane&3.
        int t = (blockIdx.x - 392) * 256 + threadIdx.x;   // 0 .. 18431
        if (t < 32 * KTAPS * 2 * 32) {
            int nt   = t / (KTAPS * 2 * 32);
            int r    = t - nt * (KTAPS * 2 * 32);
            int tap  = r / (2 * 32);
            int r2   = r - tap * (2 * 32);
            int h    = r2 >> 5;
            int lane = r2 & 31;
            int g    = lane >> 2, tig = lane & 3;
            int n    = nt * 8 + g;
            uint32_t vv[4];
#pragma unroll
            for (int q = 0; q < 2; q++) {            // kc = 2h + q
                int kc = 2 * h + q;
                uint32_t v0 = 0, v1 = 0;
#pragma unroll
                for (int j = 0; j < 4; j++) {
                    int c0 = kc * 32 + 4 * tig + j;
                    int val0 = __float2int_rn(w[((size_t)(n * CIN + c0)) * KTAPS + tap]);
                    int val1 = __float2int_rn(w[((size_t)(n * CIN + c0 + 16)) * KTAPS + tap]);
                    v0 |= (uint32_t)(val0 & 0xFF) << (8 * j);
                    v1 |= (uint32_t)(val1 & 0xFF) << (8 * j);
                }
                vv[2*q]   = v0;
                vv[2*q+1] = v1;
            }
            int4* dst = (int4*)(g_wfrag + (size_t)t * 16);
            *dst = make_int4((int)vv[0], (int)vv[1], (int)vv[2], (int)vv[3]);
        }
    }
}

// ---------------------------------------------------------------------------
// Kernel 2: implicit-GEMM conv. CTA tile M=64 x N=256, 256 threads
// (8 warps as 2M x 4N, warp tile 32x64). All 9 A-tap slabs resident in smem;
// free-running mainloop (R13, verified). Epilogue stages through smem
// (pitch 272B, conflict-free) and writes 256B-contiguous STG.128 rows.
// ---------------------------------------------------------------------------
__device__ __forceinline__ void mma_s8(int* c, const int* a, int b0, int b1) {
    asm volatile(
        "mma.sync.aligned.m16n8k32.row.col.s32.s8.s8.s32 "
        "{%0,%1,%2,%3}, {%4,%5,%6,%7}, {%8,%9}, {%0,%1,%2,%3};\n"
        : "+r"(c[0]), "+r"(c[1]), "+r"(c[2]), "+r"(c[3])
        : "r"(a[0]), "r"(a[1]), "r"(a[2]), "r"(a[3]), "r"(b0), "r"(b1));
}

#define CPA16(dst, src, sz) \
    asm volatile("cp.async.cg.shared.global [%0], [%1], 16, %2;\n" \
                 :: "r"(dst), "l"(src), "r"(sz))

__global__ void __launch_bounds__(256, 2)
conv_mma_kernel(const float* __restrict__ tbias,
                const int*   __restrict__ nshift,
                const int*   __restrict__ amin,
                const int*   __restrict__ amax,
                float*       __restrict__ out) {
    extern __shared__ __align__(16) int8_t smA[];
    const uint32_t smem_u32 = (uint32_t)__cvta_generic_to_shared(smA);

    const int tid  = threadIdx.x;
    const int lane = tid & 31;
    const int warp = tid >> 5;
    const int warpM = warp >> 2;         // 0..1 -> 32 M-rows each
    const int warpN = warp & 3;          // 0..3 -> 64 N-cols (8 n8-tiles)
    const int g   = lane >> 2;
    const int tig = lane & 3;

    const int m0  = blockIdx.x * 64;     // 3136 % 64 == 0 -> tile never spans batch
    const int b   = m0 / HWPix;
    const int hw0 = m0 - b * HWPix;

    // A-loader invariants: row = tid>>2 (0..63), quarter = tid&3 (32B each)
    const int ar = tid >> 2, aq = tid & 3;
    const int ahw = hw0 + ar;
    const int ah  = ahw / WW;
    const int aw  = ahw - ah * WW;

    // ---- load ALL 9 tap slabs up front (single group, single barrier) ----
#pragma unroll
    for (int tap = 0; tap < KTAPS; tap++) {
        const int dh = tap / 3 - 1;
        const int dw = tap % 3 - 1;
        int hs = ah + dh, ws = aw + dw;
        bool valid = ((unsigned)hs < HH) && ((unsigned)ws < WW);
        int sidx = valid ? (b * HWPix + hs * WW + ws) : 0;
        const int8_t* src = g_x8 + ((size_t)sidx << 7) + aq * 32;
        uint32_t dst = smem_u32 + tap * ABUF + ar * PA + aq * 32;
        int sz = valid ? 16 : 0;
        CPA16(dst,      src,      sz);
        CPA16(dst + 16, src + 16, sz);
    }
    asm volatile("cp.async.commit_group;\n");

    int acc[2][8][4];
#pragma unroll
    for (int i = 0; i < 2; i++)
#pragma unroll
        for (int j = 0; j < 8; j++)
#pragma unroll
            for (int k = 0; k < 4; k++) acc[i][j][k] = 0;

    // W base for this warp: nt = warpN*8 + tn.
    // addr(nt,tap,h) = ((nt*9 + tap)*2 + h)*512 + lane*16
    const int8_t* wbase = g_wfrag + (size_t)(warpN * 8) * (KTAPS * 1024)
                        + (size_t)lane * 16;

    asm volatile("cp.async.wait_group 0;\n");
    __syncthreads();      // all slabs visible to all warps

    // ---- mainloop: free-running, per half-tap load batch then 32 mmas ----
#pragma unroll 1
    for (int tap = 0; tap < KTAPS; tap++) {
        const uint32_t baseA = smem_u32 + tap * ABUF;
        const int8_t*  wt    = wbase + (size_t)tap * 1024;
#pragma unroll
        for (int h = 0; h < 2; h++) {
            // A fragments for kc = 2h, 2h+1 (4 LDSM)
            int a[2][2][4];
#pragma unroll
            for (int mi = 0; mi < 2; mi++) {
#pragma unroll
                for (int q = 0; q < 2; q++) {
                    int row = warpM * 32 + mi * 16 + (lane & 15);
                    int col = (2 * h + q) * 32 + ((lane >> 4) << 4);
                    uint32_t addr = baseA + row * PA + col;
                    asm volatile(
                        "ldmatrix.sync.aligned.m8n8.x4.shared.b16 {%0,%1,%2,%3}, [%4];\n"
                        : "=r"(a[mi][q][0]), "=r"(a[mi][q][1]),
                          "=r"(a[mi][q][2]), "=r"(a[mi][q][3])
                        : "r"(addr));
                }
            }
            // 8 independent contiguous LDG.128 (one per tn) — MLP batch
            int4 wv[8];
#pragma unroll
            for (int tn = 0; tn < 8; tn++)
                wv[tn] = __ldg((const int4*)(wt + h * 512 + (size_t)tn * (KTAPS * 1024)));
            // 32 mmas, kc-outer (acc reuse gap = 16)
#pragma unroll
            for (int q = 0; q < 2; q++) {
#pragma unroll
                for (int tn = 0; tn < 8; tn++) {
                    int b0 = q ? wv[tn].z : wv[tn].x;
                    int b1 = q ? wv[tn].w : wv[tn].y;
                    mma_s8(acc[0][tn], a[0][q], b0, b1);
                    mma_s8(acc[1][tn], a[1][q], b0, b1);
                }
            }
        }
    }

    // ---- epilogue: bias + shift + clamp, staged through smem ----
    __syncthreads();                     // A slabs dead; reuse as staging
    float* smO = (float*)smA;            // [256][OPITCH] floats (69632 B)
#pragma unroll
    for (int tn = 0; tn < 8; tn++) {
#pragma unroll
        for (int cb = 0; cb < 2; cb++) {
            int ng = warpN * 64 + tn * 8 + 2 * tig + cb;
            int tb = __float2int_rn(__ldg(&tbias[ng]));
            int sh = -__ldg(&nshift[ng]);
            int mn = __ldg(&amin[ng]);
            int mx = __ldg(&amax[ng]);
#pragma unroll
            for (int mi = 0; mi < 2; mi++) {
#pragma unroll
                for (int rh = 0; rh < 2; rh++) {
                    int v = acc[mi][tn][rh * 2 + cb];
                    v = (v + tb) >> sh;
                    v = max(mn, min(mx, v));
                    int ml = warpM * 32 + mi * 16 + rh * 8 + g;
                    smO[ng * OPITCH + ml] = (float)v;
                }
            }
        }
    }
    __syncthreads();
    // writer: half-warp per channel row -> 256B contiguous STG.128
    {
        int rsel = lane >> 4;            // 0/1 within warp
        int c16  = lane & 15;            // 16B column
        const float* obase = out + ((size_t)b * COUT) * HWPix + hw0 + c16 * 4;
#pragma unroll
        for (int i = 0; i < 16; i++) {
            int row = i * 16 + warp * 2 + rsel;      // channel 0..255
            float4 v = *(const float4*)(smO + row * OPITCH + c16 * 4);
            *(float4*)(obase + (size_t)row * HWPix) = v;
        }
    }
}

// ---------------------------------------------------------------------------
// Launch
// ---------------------------------------------------------------------------
extern "C" void kernel_launch(void* const* d_in, const int* in_sizes, int n_in,
                              void* d_out, int out_size) {
    const float* x      = (const float*)d_in[0];
    const float* weight = (const float*)d_in[1];
    const float* tbias  = (const float*)d_in[2];
    const int*   nsh    = (const int*)d_in[3];
    const int*   amin   = (const int*)d_in[4];
    const int*   amax   = (const int*)d_in[5];
    float* out = (float*)d_out;

    (void)cudaFuncSetAttribute(conv_mma_kernel,
                               cudaFuncAttributeMaxDynamicSharedMemorySize,
                               SMEMSZ);

    convert_kernel<<<464, 256>>>(x, weight);                       // 392 + 72 blocks
    conv_mma_kernel<<<BATCH * (HWPix / 64), 256, SMEMSZ>>>(tbias, nsh, amin, amax, out);
}